// round 16
// baseline (speedup 1.0000x reference)
#include <cuda_runtime.h>
#include <cuda_fp16.h>
#include <math.h>
#include <stdint.h>

// Problem constants
#define DIMK 4096
#define HQ   32
#define HKV  8
#define HD   128
#define REP  (HQ / HKV)
#define SMAX 2048
#define ATT_SCALE 0.08838834764831845f   // 1/sqrt(128)

#define NSM_CTAS 296                     // 2 CTAs x 148 SMs (persistent grid)

// ---------------------------------------------------------------------------
// Scratch (device globals: allocation-free per harness rules)
// ---------------------------------------------------------------------------
__device__ __half g_xh[(size_t)SMAX * DIMK];
__device__ __half g_oh[(size_t)SMAX * DIMK];     // attention output (fp16)
__device__ __half g_qh[(size_t)SMAX * HQ * HD];  // fp16 Q (roped, from GEMM)
__device__ __half g_kh[(size_t)SMAX * HKV * HD]; // fp16 K (roped, from GEMM)
__device__ __half g_vh[(size_t)SMAX * HKV * HD]; // fp16 V
__device__ __half g_wqh[(size_t)4096 * 4096];
__device__ __half g_wkh[(size_t)1024 * 4096];
__device__ __half g_wvh[(size_t)1024 * 4096];
__device__ __half g_woh[(size_t)4096 * 4096];

// ---------------------------------------------------------------------------
// Helpers
// ---------------------------------------------------------------------------
static __device__ __forceinline__ uint32_t smem_u32(const void* p) {
    uint32_t a;
    asm("{ .reg .u64 t; cvta.to.shared.u64 t, %1; cvt.u32.u64 %0, t; }"
        : "=r"(a) : "l"(p));
    return a;
}

static __device__ __forceinline__ void ldsm4(uint32_t& r0, uint32_t& r1,
                                             uint32_t& r2, uint32_t& r3,
                                             uint32_t addr) {
    asm volatile("ldmatrix.sync.aligned.m8n8.x4.shared.b16 {%0,%1,%2,%3}, [%4];"
                 : "=r"(r0), "=r"(r1), "=r"(r2), "=r"(r3) : "r"(addr));
}

static __device__ __forceinline__ void ldsm4t(uint32_t& r0, uint32_t& r1,
                                              uint32_t& r2, uint32_t& r3,
                                              uint32_t addr) {
    asm volatile("ldmatrix.sync.aligned.m8n8.x4.trans.shared.b16 {%0,%1,%2,%3}, [%4];"
                 : "=r"(r0), "=r"(r1), "=r"(r2), "=r"(r3) : "r"(addr));
}

static __device__ __forceinline__ void mma16816(float* c, uint32_t a0, uint32_t a1,
                                                uint32_t a2, uint32_t a3,
                                                uint32_t b0, uint32_t b1) {
    asm volatile(
        "mma.sync.aligned.m16n8k16.row.col.f32.f16.f16.f32 "
        "{%0,%1,%2,%3}, {%4,%5,%6,%7}, {%8,%9}, {%0,%1,%2,%3};"
        : "+f"(c[0]), "+f"(c[1]), "+f"(c[2]), "+f"(c[3])
        : "r"(a0), "r"(a1), "r"(a2), "r"(a3), "r"(b0), "r"(b1));
}

static __device__ __forceinline__ uint32_t pack_h2(float a, float b) {
    __half2 h = __floats2half2_rn(a, b);
    return *(uint32_t*)&h;
}

// rotate (v0,v1) by (cos,sin), round to half2
static __device__ __forceinline__ __half2 rope_h2(float v0, float v1, float2 cs) {
    return __floats2half2_rn(v0 * cs.x - v1 * cs.y, v0 * cs.y + v1 * cs.x);
}

// ---------------------------------------------------------------------------
// Fused cast: 5 fp32 regions -> fp16, one launch.
// ---------------------------------------------------------------------------
__global__ void cast_all_kernel(
        const float* __restrict__ s0, const float* __restrict__ s1,
        const float* __restrict__ s2, const float* __restrict__ s3,
        const float* __restrict__ s4,
        __half* __restrict__ d0, __half* __restrict__ d1,
        __half* __restrict__ d2, __half* __restrict__ d3,
        __half* __restrict__ d4,
        int e0, int e1, int e2, int e3, int e4) {
    const int stride = gridDim.x * blockDim.x;
    for (int i = blockIdx.x * blockDim.x + threadIdx.x; i < e4; i += stride) {
        const float* s;
        __half* d;
        int off;
        if (i < e0)      { s = s0; d = d0; off = i; }
        else if (i < e1) { s = s1; d = d1; off = i - e0; }
        else if (i < e2) { s = s2; d = d2; off = i - e1; }
        else if (i < e3) { s = s3; d = d3; off = i - e2; }
        else             { s = s4; d = d4; off = i - e3; }
        float4 v = ((const float4*)s)[off];
        uint2 o;
        o.x = pack_h2(v.x, v.y);
        o.y = pack_h2(v.z, v.w);
        *(uint2*)(d + 4 * (size_t)off) = o;
    }
}

// ---------------------------------------------------------------------------
// GEMM geometry: 128x128 CTA tile, BK=32, 8 warps (2x4), warp 64x32,
// 3 smem slots / 2-deep cp.async prefetch, single barrier per chunk,
// PERSISTENT CTAs (2/SM), tile loop.
// ---------------------------------------------------------------------------
#define GSTAGES 3
#define GBK     32
#define RS_B    80
#define GTILE_B (128 * RS_B)
#define GSTAGE_B (2 * GTILE_B)
#define GSMEM_BYTES (GSTAGES * GSTAGE_B)   // 61440

static __device__ __forceinline__ void tile_cp(uint32_t sbase,
        const __half* __restrict__ src, int r0, int kc, int K, int tid) {
#pragma unroll
    for (int i = 0; i < 2; i++) {
        int ch  = tid + i * 256;
        int r   = ch >> 2;
        int c16 = ch & 3;
        uint32_t dst = sbase + (uint32_t)(r * RS_B + c16 * 16);
        const void* g = src + (size_t)(r0 + r) * K + kc + c16 * 8;
        asm volatile("cp.async.cg.shared.global [%0], [%1], 16;"
                     :: "r"(dst), "l"(g) : "memory");
    }
}

// Shared mainloop body (compute one BK=32 chunk from slot `stg`)
#define GEMM_COMPUTE_CHUNK(stg)                                                 \
    do {                                                                        \
        const uint32_t Bt = (stg) + GTILE_B;                                    \
        _Pragma("unroll")                                                       \
        for (int k16 = 0; k16 < 2; k16++) {                                     \
            const uint32_t kB = (uint32_t)(k16 * 16 * 2);                       \
            uint32_t a[4][4];                                                   \
            _Pragma("unroll")                                                   \
            for (int mb = 0; mb < 4; mb++)                                      \
                ldsm4(a[mb][0], a[mb][1], a[mb][2], a[mb][3],                   \
                      (stg) + a_off + mb * (16 * RS_B) + kB);                   \
            uint32_t b[8];                                                      \
            ldsm4(b[0], b[1], b[2], b[3], Bt + b_off + kB);                     \
            ldsm4(b[4], b[5], b[6], b[7], Bt + b_off + 16 * RS_B + kB);         \
            _Pragma("unroll")                                                   \
            for (int mb = 0; mb < 4; mb++)                                      \
                _Pragma("unroll")                                               \
                for (int nb = 0; nb < 4; nb++)                                  \
                    mma16816(acc[mb][nb], a[mb][0], a[mb][1], a[mb][2],         \
                             a[mb][3], b[2 * nb], b[2 * nb + 1]);               \
        }                                                                       \
    } while (0)

// Full per-tile pipelined mainloop (prologue + loop).  Leaves acc filled.
#define GEMM_TILE_MAINLOOP(Aptr, Bptr, bmv, bnoff)                              \
    do {                                                                        \
        _Pragma("unroll")                                                       \
        for (int i = 0; i < 2; i++) {                                           \
            const uint32_t stg = sb + i * GSTAGE_B;                             \
            tile_cp(stg,           (Aptr), (bmv),  i * GBK, K, tid);            \
            tile_cp(stg + GTILE_B, (Bptr), (bnoff), i * GBK, K, tid);           \
            asm volatile("cp.async.commit_group;" ::: "memory");                \
        }                                                                       \
        for (int c = 0; c < NC; c++) {                                          \
            asm volatile("cp.async.wait_group 1;" ::: "memory");                \
            __syncthreads();                                                    \
            const int cn = c + 2;                                               \
            if (cn < NC) {                                                      \
                const uint32_t stgL = sb + (cn % GSTAGES) * GSTAGE_B;           \
                tile_cp(stgL,           (Aptr), (bmv),  cn * GBK, K, tid);      \
                tile_cp(stgL + GTILE_B, (Bptr), (bnoff), cn * GBK, K, tid);     \
            }                                                                   \
            asm volatile("cp.async.commit_group;" ::: "memory");                \
            const uint32_t stg = sb + (c % GSTAGES) * GSTAGE_B;                 \
            GEMM_COMPUTE_CHUNK(stg);                                            \
        }                                                                       \
        __syncthreads();  /* smem safe for next tile's prologue */              \
    } while (0)

// ---------------------------------------------------------------------------
// Fused QKV projection GEMM (persistent; single-pass fp16, RoPE for Q/K).
// Tile index t: bm = (t/48)*128; bnb = t%48 (0..31 Q, 32..39 K, 40..47 V).
// ---------------------------------------------------------------------------
__global__ __launch_bounds__(256, 2)
void gemm_qkv(const __half* __restrict__ A,
              const __half* __restrict__ Wq, const __half* __restrict__ Wk,
              const __half* __restrict__ Wv, const float* __restrict__ fc,
              __half* __restrict__ Qo, __half* __restrict__ Ko,
              __half* __restrict__ Vo, int M, int K) {
    extern __shared__ __align__(16) char smraw[];
    const uint32_t sb  = smem_u32(smraw);
    const int tid  = threadIdx.x;
    const int wid  = tid >> 5;
    const int lane = tid & 31;
    const int wm   = wid >> 2;
    const int wn   = wid & 3;

    const int a_row = wm * 64 + (lane & 15);
    const int a_colB = ((lane >> 4) * 8) * 2;
    const int b_row = wn * 32 + (lane & 7) + ((lane >> 4) * 8);
    const int b_colB = (((lane >> 3) & 1) * 8) * 2;
    const uint32_t a_off = (uint32_t)(a_row * RS_B + a_colB);
    const uint32_t b_off = (uint32_t)(b_row * RS_B + b_colB);

    const int NC = K / GBK;
    const int ntiles = (M / 128) * 48;

    for (int t = blockIdx.x; t < ntiles; t += gridDim.x) {
        const int bm  = (t / 48) * 128;
        const int bnb = t % 48;

        const __half* B;
        __half* C;
        int Nout, colbase;
        bool do_rope;
        if (bnb < 32)      { B = Wq + (size_t)bnb * 128 * K;        C = Qo; Nout = 4096; colbase = bnb * 128;        do_rope = true;  }
        else if (bnb < 40) { B = Wk + (size_t)(bnb - 32) * 128 * K; C = Ko; Nout = 1024; colbase = (bnb - 32) * 128; do_rope = true;  }
        else               { B = Wv + (size_t)(bnb - 40) * 128 * K; C = Vo; Nout = 1024; colbase = (bnb - 40) * 128; do_rope = false; }

        float acc[4][4][4];
#pragma unroll
        for (int i = 0; i < 4; i++)
#pragma unroll
            for (int j = 0; j < 4; j++)
#pragma unroll
                for (int k = 0; k < 4; k++) acc[i][j][k] = 0.f;

        GEMM_TILE_MAINLOOP(A, B, bm, 0);

        const int tr = lane >> 2;
        const int tc = (lane & 3) * 2;
#pragma unroll
        for (int mb = 0; mb < 4; mb++) {
            const int row0 = bm + wm * 64 + mb * 16 + tr;
            const int row1 = row0 + 8;
#pragma unroll
            for (int nb = 0; nb < 4; nb++) {
                const int col = colbase + wn * 32 + nb * 8 + tc;
                if (do_rope) {
                    const int d = col & (HD - 1);
                    float2 cs0 = *(const float2*)(fc + (size_t)row0 * HD + d);
                    float2 cs1 = *(const float2*)(fc + (size_t)row1 * HD + d);
                    *(__half2*)(C + (size_t)row0 * Nout + col) =
                        rope_h2(acc[mb][nb][0], acc[mb][nb][1], cs0);
                    *(__half2*)(C + (size_t)row1 * Nout + col) =
                        rope_h2(acc[mb][nb][2], acc[mb][nb][3], cs1);
                } else {
                    *(__half2*)(C + (size_t)row0 * Nout + col) =
                        __floats2half2_rn(acc[mb][nb][0], acc[mb][nb][1]);
                    *(__half2*)(C + (size_t)row1 * Nout + col) =
                        __floats2half2_rn(acc[mb][nb][2], acc[mb][nb][3]);
                }
            }
        }
    }
}

// ---------------------------------------------------------------------------
// 1-pass GEMM, fp32 out (output projection), persistent: C = A @ B^T
// ---------------------------------------------------------------------------
__global__ __launch_bounds__(256, 2)
void gemm_f16_f32(const __half* __restrict__ A, const __half* __restrict__ B,
                  float* __restrict__ C, int M, int N, int K) {
    extern __shared__ __align__(16) char smraw[];
    const uint32_t sb  = smem_u32(smraw);
    const int tid  = threadIdx.x;
    const int wid  = tid >> 5;
    const int lane = tid & 31;
    const int wm   = wid >> 2;
    const int wn   = wid & 3;

    const int a_row = wm * 64 + (lane & 15);
    const int a_colB = ((lane >> 4) * 8) * 2;
    const int b_row = wn * 32 + (lane & 7) + ((lane >> 4) * 8);
    const int b_colB = (((lane >> 3) & 1) * 8) * 2;
    const uint32_t a_off = (uint32_t)(a_row * RS_B + a_colB);
    const uint32_t b_off = (uint32_t)(b_row * RS_B + b_colB);

    const int NC = K / GBK;
    const int nbn = N / 128;
    const int ntiles = (M / 128) * nbn;

    for (int t = blockIdx.x; t < ntiles; t += gridDim.x) {
        const int bm = (t / nbn) * 128;
        const int bn = (t % nbn) * 128;

        float acc[4][4][4];
#pragma unroll
        for (int i = 0; i < 4; i++)
#pragma unroll
            for (int j = 0; j < 4; j++)
#pragma unroll
                for (int k = 0; k < 4; k++) acc[i][j][k] = 0.f;

        GEMM_TILE_MAINLOOP(A, B, bm, bn);

        const int tr = lane >> 2;
        const int tc = (lane & 3) * 2;
#pragma unroll
        for (int mb = 0; mb < 4; mb++) {
            const int row = bm + wm * 64 + mb * 16 + tr;
#pragma unroll
            for (int nb = 0; nb < 4; nb++) {
                const int col = bn + wn * 32 + nb * 8 + tc;
                float* c0 = C + (size_t)row * N + col;
                *(float2*)c0 = make_float2(acc[mb][nb][0], acc[mb][nb][1]);
                float* c1 = C + (size_t)(row + 8) * N + col;
                *(float2*)c1 = make_float2(acc[mb][nb][2], acc[mb][nb][3]);
            }
        }
    }
}

// ---------------------------------------------------------------------------
// HMMA flash attention: 128q x 64k tiles, 8 warps (256 thr), online softmax.
// Q/K/V fp16, O written fp16 at [s][h*128+d].  1 CTA/SM (105 KB smem).
// ---------------------------------------------------------------------------
#define AKS 136                               // half stride (272 B) per row
#define AQ_BYTES (128 * AKS * 2)              // 34816
#define AT_BYTES (64 * AKS * 2)               // 17408
#define ATTN_SMEM_BYTES (AQ_BYTES + 4 * AT_BYTES + 1024)

static __device__ __forceinline__ void attn_load_kv(
        uint32_t uK, uint32_t uV,
        const __half* __restrict__ Kh, const __half* __restrict__ Vh,
        int k0, int kvh, int tid) {
#pragma unroll
    for (int i = 0; i < 4; i++) {
        int ch = tid + i * 256;
        int r  = ch >> 4;
        int c  = ch & 15;
        size_t goff = (size_t)(k0 + r) * (HKV * HD) + kvh * HD + c * 8;
        uint32_t soff = (uint32_t)(r * AKS + c * 8) * 2;
        asm volatile("cp.async.cg.shared.global [%0], [%1], 16;"
                     :: "r"(uK + soff), "l"((const void*)(Kh + goff)) : "memory");
        asm volatile("cp.async.cg.shared.global [%0], [%1], 16;"
                     :: "r"(uV + soff), "l"((const void*)(Vh + goff)) : "memory");
    }
}

__global__ __launch_bounds__(256, 1)
void attn_hmma(const __half* __restrict__ Qh, const __half* __restrict__ Kh,
               const __half* __restrict__ Vh, const int* __restrict__ seqlens,
               int nseq, __half* __restrict__ Oh, int S) {
    extern __shared__ __align__(16) char smraw[];
    const uint32_t sb  = smem_u32(smraw);
    const uint32_t uQ  = sb;
    const uint32_t uK0 = sb + AQ_BYTES;
    const uint32_t uV0 = sb + AQ_BYTES + 2 * AT_BYTES;
    int* seg_s = (int*)(smraw + AQ_BYTES + 4 * AT_BYTES);

    const int tid  = threadIdx.x;
    const int wid  = tid >> 5;
    const int lane = tid & 31;
    const int h    = blockIdx.y;
    const int kvh  = h / REP;
    const int qb   = gridDim.x - 1 - (int)blockIdx.x;   // heavy blocks first
    const int q0   = qb * 128;

    int kt_lo;
    {
        int cum = 0, ss = 0;
        for (int i = 0; i < nseq; i++) {
            int nc = cum + seqlens[i];
            if (q0 < nc) { ss = cum; break; }
            cum = nc;
        }
        kt_lo = ss >> 6;
    }
    const int kt_hi = (q0 + 127) >> 6;

    // Q tile (128 rows) -> smem
#pragma unroll
    for (int i = 0; i < 8; i++) {
        int ch = tid + i * 256;
        int r  = ch >> 4;
        int c  = ch & 15;
        uint32_t dst = uQ + (uint32_t)(r * AKS + c * 8) * 2;
        const void* g = Qh + (size_t)(q0 + r) * (HQ * HD) + h * HD + c * 8;
        asm volatile("cp.async.cg.shared.global [%0], [%1], 16;"
                     :: "r"(dst), "l"(g) : "memory");
    }
    asm volatile("cp.async.commit_group;" ::: "memory");

    attn_load_kv(uK0, uV0, Kh, Vh, kt_lo * 64, kvh, tid);
    asm volatile("cp.async.commit_group;" ::: "memory");

    if (tid < 128) {
        int qg = q0 + tid;
        int cum = 0, ss = 0;
        for (int i = 0; i < nseq; i++) {
            int nc = cum + seqlens[i];
            if (qg < nc) { ss = cum; break; }
            cum = nc;
        }
        seg_s[tid] = ss;
    }

    asm volatile("cp.async.wait_group 0;" ::: "memory");
    __syncthreads();

    uint32_t qf[8][4];
    {
        const uint32_t a_off =
            (uint32_t)((wid * 16 + (lane & 15)) * AKS + (lane >> 4) * 8) * 2;
#pragma unroll
        for (int kb = 0; kb < 8; kb++)
            ldsm4(qf[kb][0], qf[kb][1], qf[kb][2], qf[kb][3],
                  uQ + a_off + kb * 32);
    }

    const uint32_t bk_off =
        (uint32_t)(((lane & 7) + ((lane >> 4) * 8)) * AKS + ((lane >> 3) & 1) * 8) * 2;
    const uint32_t bv_off =
        (uint32_t)((lane & 15) * AKS + (lane >> 4) * 8) * 2;

    const int tr  = lane >> 2;
    const int r0l = wid * 16 + tr;
    const int r0g = q0 + r0l;
    const int r1g = r0g + 8;
    const int ss0 = seg_s[r0l];
    const int ss1 = seg_s[r0l + 8];

    float oa[16][4];
#pragma unroll
    for (int i = 0; i < 16; i++)
#pragma unroll
        for (int j = 0; j < 4; j++) oa[i][j] = 0.f;
    float m0 = -1e30f, m1 = -1e30f, l0 = 0.f, l1 = 0.f;

    const int nt = kt_hi - kt_lo + 1;
    int buf = 0;
    for (int t = 0; t < nt; t++) {
        const int k0 = (kt_lo + t) * 64;
        if (t + 1 < nt)
            attn_load_kv(uK0 + (buf ^ 1) * AT_BYTES,
                         uV0 + (buf ^ 1) * AT_BYTES,
                         Kh, Vh, (kt_lo + t + 1) * 64, kvh, tid);
        asm volatile("cp.async.commit_group;" ::: "memory");
        if (t > 0) {
            if (t + 1 < nt)
                asm volatile("cp.async.wait_group 1;" ::: "memory");
            else
                asm volatile("cp.async.wait_group 0;" ::: "memory");
            __syncthreads();
        }

        const uint32_t uKb = uK0 + buf * AT_BYTES;
        const uint32_t uVb = uV0 + buf * AT_BYTES;

        float sc[8][4];
#pragma unroll
        for (int i = 0; i < 8; i++)
#pragma unroll
            for (int j = 0; j < 4; j++) sc[i][j] = 0.f;
#pragma unroll
        for (int kb = 0; kb < 8; kb++) {
#pragma unroll
            for (int nbp = 0; nbp < 4; nbp++) {
                uint32_t b0, b1, b2, b3;
                ldsm4(b0, b1, b2, b3,
                      uKb + bk_off + nbp * (16 * AKS * 2) + kb * 32);
                mma16816(sc[2 * nbp],     qf[kb][0], qf[kb][1], qf[kb][2], qf[kb][3], b0, b1);
                mma16816(sc[2 * nbp + 1], qf[kb][0], qf[kb][1], qf[kb][2], qf[kb][3], b2, b3);
            }
        }

        float mx0 = -1e30f, mx1 = -1e30f;
#pragma unroll
        for (int nb = 0; nb < 8; nb++) {
            int kbase = k0 + nb * 8 + (lane & 3) * 2;
#pragma unroll
            for (int c = 0; c < 2; c++) {
                int kg = kbase + c;
                float v0 = sc[nb][c] * ATT_SCALE;
                float v1 = sc[nb][2 + c] * ATT_SCALE;
                v0 = (kg <= r0g && kg >= ss0) ? v0 : -1e30f;
                v1 = (kg <= r1g && kg >= ss1) ? v1 : -1e30f;
                sc[nb][c] = v0; sc[nb][2 + c] = v1;
                mx0 = fmaxf(mx0, v0); mx1 = fmaxf(mx1, v1);
            }
        }
        mx0 = fmaxf(mx0, __shfl_xor_sync(0xffffffffu, mx0, 1));
        mx0 = fmaxf(mx0, __shfl_xor_sync(0xffffffffu, mx0, 2));
        mx1 = fmaxf(mx1, __shfl_xor_sync(0xffffffffu, mx1, 1));
        mx1 = fmaxf(mx1, __shfl_xor_sync(0xffffffffu, mx1, 2));

        const float m0n = fmaxf(m0, mx0);
        const float m1n = fmaxf(m1, mx1);
        const float al0 = __expf(m0 - m0n);
        const float al1 = __expf(m1 - m1n);

        float s0 = 0.f, s1 = 0.f;
#pragma unroll
        for (int nb = 0; nb < 8; nb++) {
#pragma unroll
            for (int c = 0; c < 2; c++) {
                float p0 = __expf(sc[nb][c]     - m0n);
                float p1 = __expf(sc[nb][2 + c] - m1n);
                sc[nb][c] = p0; sc[nb][2 + c] = p1;
                s0 += p0; s1 += p1;
            }
        }
        s0 += __shfl_xor_sync(0xffffffffu, s0, 1);
        s0 += __shfl_xor_sync(0xffffffffu, s0, 2);
        s1 += __shfl_xor_sync(0xffffffffu, s1, 1);
        s1 += __shfl_xor_sync(0xffffffffu, s1, 2);
        l0 = l0 * al0 + s0;
        l1 = l1 * al1 + s1;
        m0 = m0n; m1 = m1n;

#pragma unroll
        for (int nb = 0; nb < 16; nb++) {
            oa[nb][0] *= al0; oa[nb][1] *= al0;
            oa[nb][2] *= al1; oa[nb][3] *= al1;
        }

#pragma unroll
        for (int kb2 = 0; kb2 < 4; kb2++) {
            uint32_t pf0 = pack_h2(sc[2 * kb2][0],     sc[2 * kb2][1]);
            uint32_t pf1 = pack_h2(sc[2 * kb2][2],     sc[2 * kb2][3]);
            uint32_t pf2 = pack_h2(sc[2 * kb2 + 1][0], sc[2 * kb2 + 1][1]);
            uint32_t pf3 = pack_h2(sc[2 * kb2 + 1][2], sc[2 * kb2 + 1][3]);
#pragma unroll
            for (int nbp = 0; nbp < 8; nbp++) {
                uint32_t b0, b1, b2, b3;
                ldsm4t(b0, b1, b2, b3,
                       uVb + bv_off + kb2 * (16 * AKS * 2) + nbp * 32);
                mma16816(oa[2 * nbp],     pf0, pf1, pf2, pf3, b0, b1);
                mma16816(oa[2 * nbp + 1], pf0, pf1, pf2, pf3, b2, b3);
            }
        }

        __syncthreads();
        buf ^= 1;
    }

    const float inv0 = 1.f / l0;
    const float inv1 = 1.f / l1;
    __half* orow0 = Oh + (size_t)r0g * (HQ * HD) + h * HD;
    __half* orow1 = Oh + (size_t)r1g * (HQ * HD) + h * HD;
#pragma unroll
    for (int nb = 0; nb < 16; nb++) {
        int col = nb * 8 + (lane & 3) * 2;
        *(__half2*)(orow0 + col) = __floats2half2_rn(oa[nb][0] * inv0, oa[nb][1] * inv0);
        *(__half2*)(orow1 + col) = __floats2half2_rn(oa[nb][2] * inv1, oa[nb][3] * inv1);
    }
}

// ---------------------------------------------------------------------------
// Launch
// Inputs: 0:x[S,4096] 1:freqs_cis[S,64,2] 2:seqlens[int32 x nseq]
//         3:wq[4096,4096] 4:wk[1024,4096] 5:wv[1024,4096] 6:wo[4096,4096]
// Output: float32 [S, 4096]
// ---------------------------------------------------------------------------
extern "C" void kernel_launch(void* const* d_in, const int* in_sizes, int n_in,
                              void* d_out, int out_size) {
    const float* x  = (const float*)d_in[0];
    const float* fc = (const float*)d_in[1];
    const int*   sl = (const int*)d_in[2];
    const float* wq = (const float*)d_in[3];
    const float* wk = (const float*)d_in[4];
    const float* wv = (const float*)d_in[5];
    const float* wo = (const float*)d_in[6];
    float* out = (float*)d_out;

    const int S    = in_sizes[0] / DIMK;   // 2048
    const int nseq = in_sizes[2];

    __half *xh, *oh, *qh, *kh, *vh, *wqh, *wkh, *wvh, *woh;
    cudaGetSymbolAddress((void**)&xh,  g_xh);
    cudaGetSymbolAddress((void**)&oh,  g_oh);
    cudaGetSymbolAddress((void**)&qh,  g_qh);
    cudaGetSymbolAddress((void**)&kh,  g_kh);
    cudaGetSymbolAddress((void**)&vh,  g_vh);
    cudaGetSymbolAddress((void**)&wqh, g_wqh);
    cudaGetSymbolAddress((void**)&wkh, g_wkh);
    cudaGetSymbolAddress((void**)&wvh, g_wvh);
    cudaGetSymbolAddress((void**)&woh, g_woh);

    cudaFuncSetAttribute(gemm_qkv, cudaFuncAttributeMaxDynamicSharedMemorySize,
                         GSMEM_BYTES);
    cudaFuncSetAttribute(gemm_f16_f32, cudaFuncAttributeMaxDynamicSharedMemorySize,
                         GSMEM_BYTES);
    cudaFuncSetAttribute(attn_hmma, cudaFuncAttributeMaxDynamicSharedMemorySize,
                         ATTN_SMEM_BYTES);

    // Fused cast: x, wq, wk, wv, wo -> fp16 in ONE launch.
    {
        const int nx  = S * DIMK / 4;          // float4 units
        const int nwq = 4096 * 1024;
        const int nwk = 1024 * 1024;
        const int nwv = 1024 * 1024;
        const int nwo = 4096 * 1024;
        const int e0 = nx;
        const int e1 = e0 + nwq;
        const int e2 = e1 + nwk;
        const int e3 = e2 + nwv;
        const int e4 = e3 + nwo;
        const int threads = 256;
        int blocks = (e4 + threads - 1) / threads;
        if (blocks > 59200) blocks = 59200;
        cast_all_kernel<<<blocks, threads>>>(x, wq, wk, wv, wo,
                                             xh, wqh, wkh, wvh, woh,
                                             e0, e1, e2, e3, e4);
    }

    // Fused QKV projection (persistent, RoPE fused for Q/K; fp16 outputs)
    gemm_qkv<<<NSM_CTAS, 256, GSMEM_BYTES>>>(
        xh, wqh, wkh, wvh, fc, qh, kh, vh, S, DIMK);

    // Attention (HMMA, 128q tile, fp16 in/out)
    attn_hmma<<<dim3(S / 128, HQ), 256, ATTN_SMEM_BYTES>>>(qh, kh, vh, sl, nseq, oh, S);

    // Output projection (persistent, single-pass fp16, fp32 out)
    gemm_f16_f32<<<NSM_CTAS, 256, GSMEM_BYTES>>>(
        oh, woh, out, S, 4096, DIMK);
}

// round 17
// speedup vs baseline: 1.1250x; 1.1250x over previous
#include <cuda_runtime.h>
#include <cuda_fp16.h>
#include <math.h>
#include <stdint.h>

// Problem constants
#define DIMK 4096
#define HQ   32
#define HKV  8
#define HD   128
#define REP  (HQ / HKV)
#define SMAX 2048
#define ATT_SCALE 0.08838834764831845f   // 1/sqrt(128)

// ---------------------------------------------------------------------------
// Scratch (device globals: allocation-free per harness rules)
// ---------------------------------------------------------------------------
__device__ __half g_xh[(size_t)SMAX * DIMK];
__device__ __half g_oh[(size_t)SMAX * DIMK];     // attention output (fp16)
__device__ __half g_qh[(size_t)SMAX * HQ * HD];  // fp16 Q (roped, from GEMM)
__device__ __half g_kh[(size_t)SMAX * HKV * HD]; // fp16 K (roped, from GEMM)
__device__ __half g_vh[(size_t)SMAX * HKV * HD]; // fp16 V
__device__ __half g_wqh[(size_t)4096 * 4096];
__device__ __half g_wkh[(size_t)1024 * 4096];
__device__ __half g_wvh[(size_t)1024 * 4096];
__device__ __half g_woh[(size_t)4096 * 4096];

// ---------------------------------------------------------------------------
// Helpers
// ---------------------------------------------------------------------------
static __device__ __forceinline__ uint32_t smem_u32(const void* p) {
    uint32_t a;
    asm("{ .reg .u64 t; cvta.to.shared.u64 t, %1; cvt.u32.u64 %0, t; }"
        : "=r"(a) : "l"(p));
    return a;
}

static __device__ __forceinline__ void ldsm4(uint32_t& r0, uint32_t& r1,
                                             uint32_t& r2, uint32_t& r3,
                                             uint32_t addr) {
    asm volatile("ldmatrix.sync.aligned.m8n8.x4.shared.b16 {%0,%1,%2,%3}, [%4];"
                 : "=r"(r0), "=r"(r1), "=r"(r2), "=r"(r3) : "r"(addr));
}

static __device__ __forceinline__ void ldsm4t(uint32_t& r0, uint32_t& r1,
                                              uint32_t& r2, uint32_t& r3,
                                              uint32_t addr) {
    asm volatile("ldmatrix.sync.aligned.m8n8.x4.trans.shared.b16 {%0,%1,%2,%3}, [%4];"
                 : "=r"(r0), "=r"(r1), "=r"(r2), "=r"(r3) : "r"(addr));
}

static __device__ __forceinline__ void mma16816(float* c, uint32_t a0, uint32_t a1,
                                                uint32_t a2, uint32_t a3,
                                                uint32_t b0, uint32_t b1) {
    asm volatile(
        "mma.sync.aligned.m16n8k16.row.col.f32.f16.f16.f32 "
        "{%0,%1,%2,%3}, {%4,%5,%6,%7}, {%8,%9}, {%0,%1,%2,%3};"
        : "+f"(c[0]), "+f"(c[1]), "+f"(c[2]), "+f"(c[3])
        : "r"(a0), "r"(a1), "r"(a2), "r"(a3), "r"(b0), "r"(b1));
}

static __device__ __forceinline__ uint32_t pack_h2(float a, float b) {
    __half2 h = __floats2half2_rn(a, b);
    return *(uint32_t*)&h;
}

// rotate (v0,v1) by (cos,sin), round to half2
static __device__ __forceinline__ __half2 rope_h2(float v0, float v1, float2 cs) {
    return __floats2half2_rn(v0 * cs.x - v1 * cs.y, v0 * cs.y + v1 * cs.x);
}

// ---------------------------------------------------------------------------
// Fused cast: 5 fp32 regions -> fp16, one launch.
// ---------------------------------------------------------------------------
__global__ void cast_all_kernel(
        const float* __restrict__ s0, const float* __restrict__ s1,
        const float* __restrict__ s2, const float* __restrict__ s3,
        const float* __restrict__ s4,
        __half* __restrict__ d0, __half* __restrict__ d1,
        __half* __restrict__ d2, __half* __restrict__ d3,
        __half* __restrict__ d4,
        int e0, int e1, int e2, int e3, int e4) {
    const int stride = gridDim.x * blockDim.x;
    for (int i = blockIdx.x * blockDim.x + threadIdx.x; i < e4; i += stride) {
        const float* s;
        __half* d;
        int off;
        if (i < e0)      { s = s0; d = d0; off = i; }
        else if (i < e1) { s = s1; d = d1; off = i - e0; }
        else if (i < e2) { s = s2; d = d2; off = i - e1; }
        else if (i < e3) { s = s3; d = d3; off = i - e2; }
        else             { s = s4; d = d4; off = i - e3; }
        float4 v = ((const float4*)s)[off];
        uint2 o;
        o.x = pack_h2(v.x, v.y);
        o.y = pack_h2(v.z, v.w);
        *(uint2*)(d + 4 * (size_t)off) = o;
    }
}

// ---------------------------------------------------------------------------
// GEMM geometry: 128x128 CTA tile, BK=64, 8 warps (2x4), warp 64x32,
// 3 smem slots / 2-deep cp.async prefetch, single barrier per chunk, 2 CTAs/SM.
// ---------------------------------------------------------------------------
#define GSTAGES 3
#define GBK     64
#define RS_B    144                        // row stride bytes (64 fp16 + pad)
#define GTILE_B (128 * RS_B)               // 18432
#define GSTAGE_B (2 * GTILE_B)             // 36864
#define GSMEM_BYTES (GSTAGES * GSTAGE_B)   // 110592 (x2 CTA = 216KB < 228KB)

static __device__ __forceinline__ void tile_cp(uint32_t sbase,
        const __half* __restrict__ src, int r0, int kc, int K, int tid) {
#pragma unroll
    for (int i = 0; i < 4; i++) {
        int ch  = tid + i * 256;          // 0..1023
        int r   = ch >> 3;                // 0..127
        int c16 = ch & 7;                 // 16B column (8 per row)
        uint32_t dst = sbase + (uint32_t)(r * RS_B + c16 * 16);
        const void* g = src + (size_t)(r0 + r) * K + kc + c16 * 8;
        asm volatile("cp.async.cg.shared.global [%0], [%1], 16;"
                     :: "r"(dst), "l"(g) : "memory");
    }
}

// Shared mainloop body (compute one BK=64 chunk from slot `stg`)
#define GEMM_COMPUTE_CHUNK(stg)                                                 \
    do {                                                                        \
        const uint32_t Bt = (stg) + GTILE_B;                                    \
        _Pragma("unroll")                                                       \
        for (int k16 = 0; k16 < 4; k16++) {                                     \
            const uint32_t kB = (uint32_t)(k16 * 16 * 2);                       \
            uint32_t a[4][4];                                                   \
            _Pragma("unroll")                                                   \
            for (int mb = 0; mb < 4; mb++)                                      \
                ldsm4(a[mb][0], a[mb][1], a[mb][2], a[mb][3],                   \
                      (stg) + a_off + mb * (16 * RS_B) + kB);                   \
            uint32_t b[8];                                                      \
            ldsm4(b[0], b[1], b[2], b[3], Bt + b_off + kB);                     \
            ldsm4(b[4], b[5], b[6], b[7], Bt + b_off + 16 * RS_B + kB);         \
            _Pragma("unroll")                                                   \
            for (int mb = 0; mb < 4; mb++)                                      \
                _Pragma("unroll")                                               \
                for (int nb = 0; nb < 4; nb++)                                  \
                    mma16816(acc[mb][nb], a[mb][0], a[mb][1], a[mb][2],         \
                             a[mb][3], b[2 * nb], b[2 * nb + 1]);               \
        }                                                                       \
    } while (0)

// ---------------------------------------------------------------------------
// Fused QKV projection GEMM (single-pass fp16, RoPE fused for Q/K blocks).
// Grid x: 0..31 -> Q cols, 32..39 -> K cols, 40..47 -> V cols.
// ---------------------------------------------------------------------------
__global__ __launch_bounds__(256, 2)
void gemm_qkv(const __half* __restrict__ A,
              const __half* __restrict__ Wq, const __half* __restrict__ Wk,
              const __half* __restrict__ Wv, const float* __restrict__ fc,
              __half* __restrict__ Qo, __half* __restrict__ Ko,
              __half* __restrict__ Vo, int M, int K) {
    extern __shared__ __align__(16) char smraw[];
    const uint32_t sb  = smem_u32(smraw);
    const int tid  = threadIdx.x;
    const int wid  = tid >> 5;
    const int lane = tid & 31;
    const int wm   = wid >> 2;
    const int wn   = wid & 3;
    const int bm = blockIdx.y * 128;
    const int bnb = blockIdx.x;

    const __half* B;
    __half* C;
    int Nout, colbase;
    bool do_rope;
    if (bnb < 32)      { B = Wq + (size_t)bnb * 128 * K;        C = Qo; Nout = 4096; colbase = bnb * 128;        do_rope = true;  }
    else if (bnb < 40) { B = Wk + (size_t)(bnb - 32) * 128 * K; C = Ko; Nout = 1024; colbase = (bnb - 32) * 128; do_rope = true;  }
    else               { B = Wv + (size_t)(bnb - 40) * 128 * K; C = Vo; Nout = 1024; colbase = (bnb - 40) * 128; do_rope = false; }

    const int a_row = wm * 64 + (lane & 15);
    const int a_colB = ((lane >> 4) * 8) * 2;
    const int b_row = wn * 32 + (lane & 7) + ((lane >> 4) * 8);
    const int b_colB = (((lane >> 3) & 1) * 8) * 2;
    const uint32_t a_off = (uint32_t)(a_row * RS_B + a_colB);
    const uint32_t b_off = (uint32_t)(b_row * RS_B + b_colB);

    float acc[4][4][4];
#pragma unroll
    for (int i = 0; i < 4; i++)
#pragma unroll
        for (int j = 0; j < 4; j++)
#pragma unroll
            for (int k = 0; k < 4; k++) acc[i][j][k] = 0.f;

    const int NC = K / GBK;

    // Prologue: 2-deep prefetch (slots 0,1)
#pragma unroll
    for (int i = 0; i < 2; i++) {
        const uint32_t stg = sb + i * GSTAGE_B;
        tile_cp(stg,           A, bm, i * GBK, K, tid);
        tile_cp(stg + GTILE_B, B, 0,  i * GBK, K, tid);
        asm volatile("cp.async.commit_group;" ::: "memory");
    }

    for (int c = 0; c < NC; c++) {
        asm volatile("cp.async.wait_group 1;" ::: "memory");
        __syncthreads();

        const int cn = c + 2;
        if (cn < NC) {
            const uint32_t stgL = sb + (cn % GSTAGES) * GSTAGE_B;
            tile_cp(stgL,           A, bm, cn * GBK, K, tid);
            tile_cp(stgL + GTILE_B, B, 0,  cn * GBK, K, tid);
        }
        asm volatile("cp.async.commit_group;" ::: "memory");

        const uint32_t stg = sb + (c % GSTAGES) * GSTAGE_B;
        GEMM_COMPUTE_CHUNK(stg);
    }

    const int tr = lane >> 2;
    const int tc = (lane & 3) * 2;
#pragma unroll
    for (int mb = 0; mb < 4; mb++) {
        const int row0 = bm + wm * 64 + mb * 16 + tr;
        const int row1 = row0 + 8;
#pragma unroll
        for (int nb = 0; nb < 4; nb++) {
            const int col = colbase + wn * 32 + nb * 8 + tc;
            if (do_rope) {
                const int d = col & (HD - 1);
                float2 cs0 = *(const float2*)(fc + (size_t)row0 * HD + d);
                float2 cs1 = *(const float2*)(fc + (size_t)row1 * HD + d);
                *(__half2*)(C + (size_t)row0 * Nout + col) =
                    rope_h2(acc[mb][nb][0], acc[mb][nb][1], cs0);
                *(__half2*)(C + (size_t)row1 * Nout + col) =
                    rope_h2(acc[mb][nb][2], acc[mb][nb][3], cs1);
            } else {
                *(__half2*)(C + (size_t)row0 * Nout + col) =
                    __floats2half2_rn(acc[mb][nb][0], acc[mb][nb][1]);
                *(__half2*)(C + (size_t)row1 * Nout + col) =
                    __floats2half2_rn(acc[mb][nb][2], acc[mb][nb][3]);
            }
        }
    }
}

// ---------------------------------------------------------------------------
// 1-pass GEMM, fp32 out (output projection): C = A @ B^T
// ---------------------------------------------------------------------------
__global__ __launch_bounds__(256, 2)
void gemm_f16_f32(const __half* __restrict__ A, const __half* __restrict__ B,
                  float* __restrict__ C, int M, int N, int K) {
    extern __shared__ __align__(16) char smraw[];
    const uint32_t sb  = smem_u32(smraw);
    const int tid  = threadIdx.x;
    const int wid  = tid >> 5;
    const int lane = tid & 31;
    const int wm   = wid >> 2;
    const int wn   = wid & 3;
    const int bm = blockIdx.y * 128;
    const int bn = blockIdx.x * 128;

    const int a_row = wm * 64 + (lane & 15);
    const int a_colB = ((lane >> 4) * 8) * 2;
    const int b_row = wn * 32 + (lane & 7) + ((lane >> 4) * 8);
    const int b_colB = (((lane >> 3) & 1) * 8) * 2;
    const uint32_t a_off = (uint32_t)(a_row * RS_B + a_colB);
    const uint32_t b_off = (uint32_t)(b_row * RS_B + b_colB);

    float acc[4][4][4];
#pragma unroll
    for (int i = 0; i < 4; i++)
#pragma unroll
        for (int j = 0; j < 4; j++)
#pragma unroll
            for (int k = 0; k < 4; k++) acc[i][j][k] = 0.f;

    const int NC = K / GBK;

#pragma unroll
    for (int i = 0; i < 2; i++) {
        const uint32_t stg = sb + i * GSTAGE_B;
        tile_cp(stg,           A, bm, i * GBK, K, tid);
        tile_cp(stg + GTILE_B, B, bn, i * GBK, K, tid);
        asm volatile("cp.async.commit_group;" ::: "memory");
    }

    for (int c = 0; c < NC; c++) {
        asm volatile("cp.async.wait_group 1;" ::: "memory");
        __syncthreads();

        const int cn = c + 2;
        if (cn < NC) {
            const uint32_t stgL = sb + (cn % GSTAGES) * GSTAGE_B;
            tile_cp(stgL,           A, bm, cn * GBK, K, tid);
            tile_cp(stgL + GTILE_B, B, bn, cn * GBK, K, tid);
        }
        asm volatile("cp.async.commit_group;" ::: "memory");

        const uint32_t stg = sb + (c % GSTAGES) * GSTAGE_B;
        GEMM_COMPUTE_CHUNK(stg);
    }

    const int tr = lane >> 2;
    const int tc = (lane & 3) * 2;
#pragma unroll
    for (int mb = 0; mb < 4; mb++) {
        const int row = bm + wm * 64 + mb * 16 + tr;
#pragma unroll
        for (int nb = 0; nb < 4; nb++) {
            const int col = bn + wn * 32 + nb * 8 + tc;
            float* c0 = C + (size_t)row * N + col;
            *(float2*)c0 = make_float2(acc[mb][nb][0], acc[mb][nb][1]);
            float* c1 = C + (size_t)(row + 8) * N + col;
            *(float2*)c1 = make_float2(acc[mb][nb][2], acc[mb][nb][3]);
        }
    }
}

// ---------------------------------------------------------------------------
// HMMA flash attention: 128q x 64k tiles, 8 warps (256 thr), online softmax.
// Q/K/V fp16, O written fp16 at [s][h*128+d].  1 CTA/SM (105 KB smem).
// ---------------------------------------------------------------------------
#define AKS 136                               // half stride (272 B) per row
#define AQ_BYTES (128 * AKS * 2)              // 34816
#define AT_BYTES (64 * AKS * 2)               // 17408
#define ATTN_SMEM_BYTES (AQ_BYTES + 4 * AT_BYTES + 1024)

static __device__ __forceinline__ void attn_load_kv(
        uint32_t uK, uint32_t uV,
        const __half* __restrict__ Kh, const __half* __restrict__ Vh,
        int k0, int kvh, int tid) {
#pragma unroll
    for (int i = 0; i < 4; i++) {
        int ch = tid + i * 256;
        int r  = ch >> 4;
        int c  = ch & 15;
        size_t goff = (size_t)(k0 + r) * (HKV * HD) + kvh * HD + c * 8;
        uint32_t soff = (uint32_t)(r * AKS + c * 8) * 2;
        asm volatile("cp.async.cg.shared.global [%0], [%1], 16;"
                     :: "r"(uK + soff), "l"((const void*)(Kh + goff)) : "memory");
        asm volatile("cp.async.cg.shared.global [%0], [%1], 16;"
                     :: "r"(uV + soff), "l"((const void*)(Vh + goff)) : "memory");
    }
}

__global__ __launch_bounds__(256, 1)
void attn_hmma(const __half* __restrict__ Qh, const __half* __restrict__ Kh,
               const __half* __restrict__ Vh, const int* __restrict__ seqlens,
               int nseq, __half* __restrict__ Oh, int S) {
    extern __shared__ __align__(16) char smraw[];
    const uint32_t sb  = smem_u32(smraw);
    const uint32_t uQ  = sb;
    const uint32_t uK0 = sb + AQ_BYTES;
    const uint32_t uV0 = sb + AQ_BYTES + 2 * AT_BYTES;
    int* seg_s = (int*)(smraw + AQ_BYTES + 4 * AT_BYTES);

    const int tid  = threadIdx.x;
    const int wid  = tid >> 5;
    const int lane = tid & 31;
    const int h    = blockIdx.y;
    const int kvh  = h / REP;
    const int qb   = gridDim.x - 1 - (int)blockIdx.x;   // heavy blocks first
    const int q0   = qb * 128;

    int kt_lo;
    {
        int cum = 0, ss = 0;
        for (int i = 0; i < nseq; i++) {
            int nc = cum + seqlens[i];
            if (q0 < nc) { ss = cum; break; }
            cum = nc;
        }
        kt_lo = ss >> 6;
    }
    const int kt_hi = (q0 + 127) >> 6;

    // Q tile (128 rows) -> smem
#pragma unroll
    for (int i = 0; i < 8; i++) {
        int ch = tid + i * 256;
        int r  = ch >> 4;
        int c  = ch & 15;
        uint32_t dst = uQ + (uint32_t)(r * AKS + c * 8) * 2;
        const void* g = Qh + (size_t)(q0 + r) * (HQ * HD) + h * HD + c * 8;
        asm volatile("cp.async.cg.shared.global [%0], [%1], 16;"
                     :: "r"(dst), "l"(g) : "memory");
    }
    asm volatile("cp.async.commit_group;" ::: "memory");

    attn_load_kv(uK0, uV0, Kh, Vh, kt_lo * 64, kvh, tid);
    asm volatile("cp.async.commit_group;" ::: "memory");

    if (tid < 128) {
        int qg = q0 + tid;
        int cum = 0, ss = 0;
        for (int i = 0; i < nseq; i++) {
            int nc = cum + seqlens[i];
            if (qg < nc) { ss = cum; break; }
            cum = nc;
        }
        seg_s[tid] = ss;
    }

    asm volatile("cp.async.wait_group 0;" ::: "memory");
    __syncthreads();

    uint32_t qf[8][4];
    {
        const uint32_t a_off =
            (uint32_t)((wid * 16 + (lane & 15)) * AKS + (lane >> 4) * 8) * 2;
#pragma unroll
        for (int kb = 0; kb < 8; kb++)
            ldsm4(qf[kb][0], qf[kb][1], qf[kb][2], qf[kb][3],
                  uQ + a_off + kb * 32);
    }

    const uint32_t bk_off =
        (uint32_t)(((lane & 7) + ((lane >> 4) * 8)) * AKS + ((lane >> 3) & 1) * 8) * 2;
    const uint32_t bv_off =
        (uint32_t)((lane & 15) * AKS + (lane >> 4) * 8) * 2;

    const int tr  = lane >> 2;
    const int r0l = wid * 16 + tr;
    const int r0g = q0 + r0l;
    const int r1g = r0g + 8;
    const int ss0 = seg_s[r0l];
    const int ss1 = seg_s[r0l + 8];

    float oa[16][4];
#pragma unroll
    for (int i = 0; i < 16; i++)
#pragma unroll
        for (int j = 0; j < 4; j++) oa[i][j] = 0.f;
    float m0 = -1e30f, m1 = -1e30f, l0 = 0.f, l1 = 0.f;

    const int nt = kt_hi - kt_lo + 1;
    int buf = 0;
    for (int t = 0; t < nt; t++) {
        const int k0 = (kt_lo + t) * 64;
        if (t + 1 < nt)
            attn_load_kv(uK0 + (buf ^ 1) * AT_BYTES,
                         uV0 + (buf ^ 1) * AT_BYTES,
                         Kh, Vh, (kt_lo + t + 1) * 64, kvh, tid);
        asm volatile("cp.async.commit_group;" ::: "memory");
        if (t > 0) {
            if (t + 1 < nt)
                asm volatile("cp.async.wait_group 1;" ::: "memory");
            else
                asm volatile("cp.async.wait_group 0;" ::: "memory");
            __syncthreads();
        }

        const uint32_t uKb = uK0 + buf * AT_BYTES;
        const uint32_t uVb = uV0 + buf * AT_BYTES;

        float sc[8][4];
#pragma unroll
        for (int i = 0; i < 8; i++)
#pragma unroll
            for (int j = 0; j < 4; j++) sc[i][j] = 0.f;
#pragma unroll
        for (int kb = 0; kb < 8; kb++) {
#pragma unroll
            for (int nbp = 0; nbp < 4; nbp++) {
                uint32_t b0, b1, b2, b3;
                ldsm4(b0, b1, b2, b3,
                      uKb + bk_off + nbp * (16 * AKS * 2) + kb * 32);
                mma16816(sc[2 * nbp],     qf[kb][0], qf[kb][1], qf[kb][2], qf[kb][3], b0, b1);
                mma16816(sc[2 * nbp + 1], qf[kb][0], qf[kb][1], qf[kb][2], qf[kb][3], b2, b3);
            }
        }

        float mx0 = -1e30f, mx1 = -1e30f;
#pragma unroll
        for (int nb = 0; nb < 8; nb++) {
            int kbase = k0 + nb * 8 + (lane & 3) * 2;
#pragma unroll
            for (int c = 0; c < 2; c++) {
                int kg = kbase + c;
                float v0 = sc[nb][c] * ATT_SCALE;
                float v1 = sc[nb][2 + c] * ATT_SCALE;
                v0 = (kg <= r0g && kg >= ss0) ? v0 : -1e30f;
                v1 = (kg <= r1g && kg >= ss1) ? v1 : -1e30f;
                sc[nb][c] = v0; sc[nb][2 + c] = v1;
                mx0 = fmaxf(mx0, v0); mx1 = fmaxf(mx1, v1);
            }
        }
        mx0 = fmaxf(mx0, __shfl_xor_sync(0xffffffffu, mx0, 1));
        mx0 = fmaxf(mx0, __shfl_xor_sync(0xffffffffu, mx0, 2));
        mx1 = fmaxf(mx1, __shfl_xor_sync(0xffffffffu, mx1, 1));
        mx1 = fmaxf(mx1, __shfl_xor_sync(0xffffffffu, mx1, 2));

        const float m0n = fmaxf(m0, mx0);
        const float m1n = fmaxf(m1, mx1);
        const float al0 = __expf(m0 - m0n);
        const float al1 = __expf(m1 - m1n);

        float s0 = 0.f, s1 = 0.f;
#pragma unroll
        for (int nb = 0; nb < 8; nb++) {
#pragma unroll
            for (int c = 0; c < 2; c++) {
                float p0 = __expf(sc[nb][c]     - m0n);
                float p1 = __expf(sc[nb][2 + c] - m1n);
                sc[nb][c] = p0; sc[nb][2 + c] = p1;
                s0 += p0; s1 += p1;
            }
        }
        s0 += __shfl_xor_sync(0xffffffffu, s0, 1);
        s0 += __shfl_xor_sync(0xffffffffu, s0, 2);
        s1 += __shfl_xor_sync(0xffffffffu, s1, 1);
        s1 += __shfl_xor_sync(0xffffffffu, s1, 2);
        l0 = l0 * al0 + s0;
        l1 = l1 * al1 + s1;
        m0 = m0n; m1 = m1n;

#pragma unroll
        for (int nb = 0; nb < 16; nb++) {
            oa[nb][0] *= al0; oa[nb][1] *= al0;
            oa[nb][2] *= al1; oa[nb][3] *= al1;
        }

#pragma unroll
        for (int kb2 = 0; kb2 < 4; kb2++) {
            uint32_t pf0 = pack_h2(sc[2 * kb2][0],     sc[2 * kb2][1]);
            uint32_t pf1 = pack_h2(sc[2 * kb2][2],     sc[2 * kb2][3]);
            uint32_t pf2 = pack_h2(sc[2 * kb2 + 1][0], sc[2 * kb2 + 1][1]);
            uint32_t pf3 = pack_h2(sc[2 * kb2 + 1][2], sc[2 * kb2 + 1][3]);
#pragma unroll
            for (int nbp = 0; nbp < 8; nbp++) {
                uint32_t b0, b1, b2, b3;
                ldsm4t(b0, b1, b2, b3,
                       uVb + bv_off + kb2 * (16 * AKS * 2) + nbp * 32);
                mma16816(oa[2 * nbp],     pf0, pf1, pf2, pf3, b0, b1);
                mma16816(oa[2 * nbp + 1], pf0, pf1, pf2, pf3, b2, b3);
            }
        }

        __syncthreads();
        buf ^= 1;
    }

    const float inv0 = 1.f / l0;
    const float inv1 = 1.f / l1;
    __half* orow0 = Oh + (size_t)r0g * (HQ * HD) + h * HD;
    __half* orow1 = Oh + (size_t)r1g * (HQ * HD) + h * HD;
#pragma unroll
    for (int nb = 0; nb < 16; nb++) {
        int col = nb * 8 + (lane & 3) * 2;
        *(__half2*)(orow0 + col) = __floats2half2_rn(oa[nb][0] * inv0, oa[nb][1] * inv0);
        *(__half2*)(orow1 + col) = __floats2half2_rn(oa[nb][2] * inv1, oa[nb][3] * inv1);
    }
}

// ---------------------------------------------------------------------------
// Launch
// Inputs: 0:x[S,4096] 1:freqs_cis[S,64,2] 2:seqlens[int32 x nseq]
//         3:wq[4096,4096] 4:wk[1024,4096] 5:wv[1024,4096] 6:wo[4096,4096]
// Output: float32 [S, 4096]
// ---------------------------------------------------------------------------
extern "C" void kernel_launch(void* const* d_in, const int* in_sizes, int n_in,
                              void* d_out, int out_size) {
    const float* x  = (const float*)d_in[0];
    const float* fc = (const float*)d_in[1];
    const int*   sl = (const int*)d_in[2];
    const float* wq = (const float*)d_in[3];
    const float* wk = (const float*)d_in[4];
    const float* wv = (const float*)d_in[5];
    const float* wo = (const float*)d_in[6];
    float* out = (float*)d_out;

    const int S    = in_sizes[0] / DIMK;   // 2048
    const int nseq = in_sizes[2];

    __half *xh, *oh, *qh, *kh, *vh, *wqh, *wkh, *wvh, *woh;
    cudaGetSymbolAddress((void**)&xh,  g_xh);
    cudaGetSymbolAddress((void**)&oh,  g_oh);
    cudaGetSymbolAddress((void**)&qh,  g_qh);
    cudaGetSymbolAddress((void**)&kh,  g_kh);
    cudaGetSymbolAddress((void**)&vh,  g_vh);
    cudaGetSymbolAddress((void**)&wqh, g_wqh);
    cudaGetSymbolAddress((void**)&wkh, g_wkh);
    cudaGetSymbolAddress((void**)&wvh, g_wvh);
    cudaGetSymbolAddress((void**)&woh, g_woh);

    cudaFuncSetAttribute(gemm_qkv, cudaFuncAttributeMaxDynamicSharedMemorySize,
                         GSMEM_BYTES);
    cudaFuncSetAttribute(gemm_f16_f32, cudaFuncAttributeMaxDynamicSharedMemorySize,
                         GSMEM_BYTES);
    cudaFuncSetAttribute(attn_hmma, cudaFuncAttributeMaxDynamicSharedMemorySize,
                         ATTN_SMEM_BYTES);

    // Fused cast: x, wq, wk, wv, wo -> fp16 in ONE launch.
    {
        const int nx  = S * DIMK / 4;          // float4 units
        const int nwq = 4096 * 1024;
        const int nwk = 1024 * 1024;
        const int nwv = 1024 * 1024;
        const int nwo = 4096 * 1024;
        const int e0 = nx;
        const int e1 = e0 + nwq;
        const int e2 = e1 + nwk;
        const int e3 = e2 + nwv;
        const int e4 = e3 + nwo;
        const int threads = 256;
        int blocks = (e4 + threads - 1) / threads;
        if (blocks > 59200) blocks = 59200;
        cast_all_kernel<<<blocks, threads>>>(x, wq, wk, wv, wo,
                                             xh, wqh, wkh, wvh, woh,
                                             e0, e1, e2, e3, e4);
    }

    // Fused QKV projection (RoPE fused for Q/K; fp16 outputs)
    gemm_qkv<<<dim3(48, S / 128), 256, GSMEM_BYTES>>>(
        xh, wqh, wkh, wvh, fc, qh, kh, vh, S, DIMK);

    // Attention (HMMA, 128q tile, fp16 in/out)
    attn_hmma<<<dim3(S / 128, HQ), 256, ATTN_SMEM_BYTES>>>(qh, kh, vh, sl, nseq, oh, S);

    // Output projection (single-pass fp16, fp32 out)
    gemm_f16_f32<<<dim3(4096 / 128, S / 128), 256, GSMEM_BYTES>>>(
        oh, woh, out, S, 4096, DIMK);
}